// round 3
// baseline (speedup 1.0000x reference)
#include <cuda_runtime.h>
#include <math.h>

#define B_   32
#define NN   1024
#define FIN  512
#define H1_  256
#define H2_  128

typedef unsigned long long ull;

// ---------------- scratch (device globals; no allocation allowed) ----------
__device__ float d_h1[B_ * NN * H1_];
__device__ float d_g1[B_ * NN * H1_];
__device__ float d_h2[B_ * NN * H2_];
__device__ float d_el[B_ * NN];
__device__ float d_er[B_ * NN];
__device__ float d_stat[B_ * 2];
__device__ float d_gv[B_ * NN];

__device__ __forceinline__ ull dup2(float x) {
    ull d;
    unsigned u = __float_as_uint(x);
    asm("mov.b64 %0, {%1, %1};" : "=l"(d) : "r"(u));
    return d;
}
__device__ __forceinline__ void fma2(ull& acc, ull a, ull b) {
    asm("fma.rn.f32x2 %0, %1, %2, %0;" : "+l"(acc) : "l"(a), "l"(b));
}
__device__ __forceinline__ void unpack2(ull v, float& lo, float& hi) {
    unsigned a, b;
    asm("mov.b64 {%0, %1}, %2;" : "=r"(a), "=r"(b) : "l"(v));
    lo = __uint_as_float(a);
    hi = __uint_as_float(b);
}
__device__ __forceinline__ ull pack2(float lo, float hi) {
    ull d;
    asm("mov.b64 %0, {%1, %2};" : "=l"(d) : "r"(__float_as_uint(lo)), "r"(__float_as_uint(hi)));
    return d;
}
__device__ __forceinline__ float attf(float x, float mn, float kk) {
    float lr = x >= 0.f ? x : 0.01f * x;
    return 1.f / (1.f + __expf(-(fmaf(lr - mn, kk, -20.f))));
}

// ---------------- warp-tiled packed-f32x2 SGEMM ------------------------------
// C[M,N] = A[M,K] @ B[K,N]. Block tile 128x128, BK=16, 256 threads.
// Warps 4(row)x2(col); lanes 4(row)x8(col); per-thread 8x8 (32 f32x2 accs).
// MODE: 0 = A from global; 1 = A = att(el,er,stat) computed on the fly;
//       2 = like 1 but also writes the att tile to attOut (requires gridDim.x==1).
// EPI:  0 = none, 1 = ELU.
template <int MODE, int EPI>
__global__ void __launch_bounds__(256, 2)
sgemm_k(const float* __restrict__ A, const float* __restrict__ Bm,
        float* __restrict__ C, int N, int K,
        long long sA, long long sB, long long sC,
        const float* __restrict__ el, const float* __restrict__ er,
        const float* __restrict__ stat, float* __restrict__ attOut)
{
    __shared__ ull   As[16][128];   // A values pre-duplicated {a,a}
    __shared__ float Bs[16][128];

    const int bz = blockIdx.z;
    if (MODE == 0) A += (long long)bz * sA;
    Bm += (long long)bz * sB;
    C  += (long long)bz * sC;

    const int m0 = blockIdx.y * 128;
    const int n0 = blockIdx.x * 128;
    const int tid  = threadIdx.x;
    const int warp = tid >> 5, lane = tid & 31;
    const int mb = (warp >> 1) * 32 + (lane >> 3) * 8;  // thread row base in tile
    const int nb = (warp & 1) * 64 + (lane & 7) * 8;    // thread col base in tile

    // producer indices
    const int arow = tid >> 1;          // 0..127
    const int akq  = (tid & 1) * 8;     // k offset 0 or 8
    const int brow = tid >> 4;          // 0..15
    const int bcol = (tid & 15) * 8;    // 0..120

    float elv = 0.f, mn = 0.f, kk = 0.f;
    if (MODE != 0) {
        elv = el[bz * NN + m0 + arow];
        mn  = stat[bz * 2 + 0];
        kk  = stat[bz * 2 + 1];
    }

    ull acc[8][4] = {};
    float4 pa0, pa1, pb0, pb1;

    // ---- producer: fetch/compute next tile into registers ----
    auto produce = [&](int k0) {
        if (MODE == 0) {
            const float* Ap = &A[(long long)(m0 + arow) * K + k0 + akq];
            pa0 = *(const float4*)Ap;
            pa1 = *(const float4*)(Ap + 4);
        } else {
            const float* erp = &er[bz * NN + k0 + akq];
            float4 e0 = *(const float4*)erp;
            float4 e1 = *(const float4*)(erp + 4);
            pa0.x = attf(elv + e0.x, mn, kk);
            pa0.y = attf(elv + e0.y, mn, kk);
            pa0.z = attf(elv + e0.z, mn, kk);
            pa0.w = attf(elv + e0.w, mn, kk);
            pa1.x = attf(elv + e1.x, mn, kk);
            pa1.y = attf(elv + e1.y, mn, kk);
            pa1.z = attf(elv + e1.z, mn, kk);
            pa1.w = attf(elv + e1.w, mn, kk);
            if (MODE == 2) {
                float* op = &attOut[(long long)bz * NN * NN +
                                    (long long)(m0 + arow) * NN + k0 + akq];
                *(float4*)op       = pa0;
                *(float4*)(op + 4) = pa1;
            }
        }
        const float* Bp = &Bm[(long long)(k0 + brow) * N + n0 + bcol];
        pb0 = *(const float4*)Bp;
        pb1 = *(const float4*)(Bp + 4);
    };

    auto store_smem = [&]() {
        As[akq + 0][arow] = dup2(pa0.x);
        As[akq + 1][arow] = dup2(pa0.y);
        As[akq + 2][arow] = dup2(pa0.z);
        As[akq + 3][arow] = dup2(pa0.w);
        As[akq + 4][arow] = dup2(pa1.x);
        As[akq + 5][arow] = dup2(pa1.y);
        As[akq + 6][arow] = dup2(pa1.z);
        As[akq + 7][arow] = dup2(pa1.w);
        *(float4*)&Bs[brow][bcol]     = pb0;
        *(float4*)&Bs[brow][bcol + 4] = pb1;
    };

    auto compute16 = [&]() {
#pragma unroll
        for (int k = 0; k < 16; k++) {
            ulonglong2 a01 = *(const ulonglong2*)&As[k][mb + 0];
            ulonglong2 a23 = *(const ulonglong2*)&As[k][mb + 2];
            ulonglong2 a45 = *(const ulonglong2*)&As[k][mb + 4];
            ulonglong2 a67 = *(const ulonglong2*)&As[k][mb + 6];
            ulonglong2 bq0 = *(const ulonglong2*)&Bs[k][nb];
            ulonglong2 bq1 = *(const ulonglong2*)&Bs[k][nb + 4];
            ull av[8] = {a01.x, a01.y, a23.x, a23.y, a45.x, a45.y, a67.x, a67.y};
            ull bv[4] = {bq0.x, bq0.y, bq1.x, bq1.y};
#pragma unroll
            for (int i = 0; i < 8; i++) {
#pragma unroll
                for (int j = 0; j < 4; j++) fma2(acc[i][j], av[i], bv[j]);
            }
        }
    };

    // ---- main loop: reg-prefetch next tile while computing current ----
    produce(0);
    store_smem();
    __syncthreads();
    for (int k0 = 16; k0 < K; k0 += 16) {
        produce(k0);
        compute16();
        __syncthreads();
        store_smem();
        __syncthreads();
    }
    compute16();

    // ---- epilogue ----
#pragma unroll
    for (int i = 0; i < 8; i++) {
        const int m = m0 + mb + i;
        float* Crow = &C[(long long)m * N + n0 + nb];
        if (EPI == 1) {
#pragma unroll
            for (int j = 0; j < 4; j++) {
                float lo, hi;
                unpack2(acc[i][j], lo, hi);
                lo = lo > 0.f ? lo : (__expf(lo) - 1.f);
                hi = hi > 0.f ? hi : (__expf(hi) - 1.f);
                acc[i][j] = pack2(lo, hi);
            }
        }
        ulonglong2 v0; v0.x = acc[i][0]; v0.y = acc[i][1];
        ulonglong2 v1; v1.x = acc[i][2]; v1.y = acc[i][3];
        *(ulonglong2*)(Crow)     = v0;
        *(ulonglong2*)(Crow + 4) = v1;
    }
}

// ---------------- per-row dual dot: el = h.aL, er = h.aR --------------------
__global__ void rowdot(const float* __restrict__ h, const float* __restrict__ a,
                       float* __restrict__ el, float* __restrict__ er, int Fo)
{
    const int row  = (blockIdx.x * blockDim.x + threadIdx.x) >> 5;
    const int lane = threadIdx.x & 31;
    const float* hp = h + (long long)row * Fo;
    float sl = 0.f, sr = 0.f;
    for (int c = lane; c < Fo; c += 32) {
        float v = hp[c];
        sl = fmaf(v, a[c], sl);
        sr = fmaf(v, a[Fo + c], sr);
    }
#pragma unroll
    for (int o = 16; o; o >>= 1) {
        sl += __shfl_xor_sync(0xFFFFFFFFu, sl, o);
        sr += __shfl_xor_sync(0xFFFFFFFFu, sr, o);
    }
    if (lane == 0) { el[row] = sl; er[row] = sr; }
}

// ---------------- per-batch min/max of separable e --------------------------
__global__ void minmax_stats(const float* __restrict__ el, const float* __restrict__ er,
                             float* __restrict__ stat)
{
    const int b = blockIdx.x;
    const int tid = threadIdx.x;
    float mnl = 1e30f, mxl = -1e30f, mnr = 1e30f, mxr = -1e30f;
    for (int i = tid; i < NN; i += 256) {
        float l = el[b * NN + i], r = er[b * NN + i];
        mnl = fminf(mnl, l); mxl = fmaxf(mxl, l);
        mnr = fminf(mnr, r); mxr = fmaxf(mxr, r);
    }
#pragma unroll
    for (int o = 16; o; o >>= 1) {
        mnl = fminf(mnl, __shfl_xor_sync(0xFFFFFFFFu, mnl, o));
        mxl = fmaxf(mxl, __shfl_xor_sync(0xFFFFFFFFu, mxl, o));
        mnr = fminf(mnr, __shfl_xor_sync(0xFFFFFFFFu, mnr, o));
        mxr = fmaxf(mxr, __shfl_xor_sync(0xFFFFFFFFu, mxr, o));
    }
    __shared__ float s[4][8];
    const int w = tid >> 5, lane = tid & 31;
    if (lane == 0) { s[0][w] = mnl; s[1][w] = mxl; s[2][w] = mnr; s[3][w] = mxr; }
    __syncthreads();
    if (tid == 0) {
        float a0 = s[0][0], a1 = s[1][0], a2 = s[2][0], a3 = s[3][0];
#pragma unroll
        for (int i = 1; i < 8; i++) {
            a0 = fminf(a0, s[0][i]); a1 = fmaxf(a1, s[1][i]);
            a2 = fminf(a2, s[2][i]); a3 = fmaxf(a3, s[3][i]);
        }
        float lo = a0 + a2, hi = a1 + a3;
        float mn = lo >= 0.f ? lo : 0.01f * lo;
        float mx = hi >= 0.f ? hi : 0.01f * hi;
        stat[b * 2 + 0] = mn;
        stat[b * 2 + 1] = 30.f / (mx - mn);
    }
}

// ---------------- gv = g2 @ Wg ----------------------------------------------
__global__ void gv_kernel(const float* __restrict__ g2, const float* __restrict__ Wg,
                          float* __restrict__ gv)
{
    const int row  = (blockIdx.x * blockDim.x + threadIdx.x) >> 5;
    const int lane = threadIdx.x & 31;
    const float* gp = g2 + (long long)row * H2_;
    float s = fmaf(gp[lane], Wg[lane], gp[lane + 32] * Wg[lane + 32]);
    s = fmaf(gp[lane + 64], Wg[lane + 64], s);
    s = fmaf(gp[lane + 96], Wg[lane + 96], s);
#pragma unroll
    for (int o = 16; o; o >>= 1) s += __shfl_xor_sync(0xFFFFFFFFu, s, o);
    if (lane == 0) gv[row] = s;
}

// ---------------- out = leaky(fc2 @ gv + bg) ----------------------------------
__global__ void z_kernel(const float* __restrict__ fc2, const float* __restrict__ gv,
                         const float* __restrict__ bg, float* __restrict__ out)
{
    const int row  = (blockIdx.x * blockDim.x + threadIdx.x) >> 5;
    const int lane = threadIdx.x & 31;
    const int b = row >> 10;
    const float* fr = fc2 + (long long)row * NN;
    const float* gr = gv + b * NN;
    float s = 0.f;
#pragma unroll
    for (int j = lane * 4; j < NN; j += 128) {
        float4 f = *(const float4*)&fr[j];
        float4 g = *(const float4*)&gr[j];
        s = fmaf(f.x, g.x, s); s = fmaf(f.y, g.y, s);
        s = fmaf(f.z, g.z, s); s = fmaf(f.w, g.w, s);
    }
#pragma unroll
    for (int o = 16; o; o >>= 1) s += __shfl_xor_sync(0xFFFFFFFFu, s, o);
    if (lane == 0) {
        float z = s + bg[0];
        out[row] = z >= 0.f ? z : 0.01f * z;
    }
}

// ---------------------------------------------------------------------------
static float* sym_f(const void* s)
{
    void* p = nullptr;
    cudaGetSymbolAddress(&p, s);
    return (float*)p;
}

extern "C" void kernel_launch(void* const* d_in, const int* in_sizes, int n_in,
                              void* d_out, int out_size)
{
    const float* x  = (const float*)d_in[0];
    const float* W1 = (const float*)d_in[2];
    const float* a1 = (const float*)d_in[3];
    const float* W2 = (const float*)d_in[4];
    const float* a2 = (const float*)d_in[5];
    const float* Wg = (const float*)d_in[6];
    const float* bg = (const float*)d_in[7];

    float* out = (float*)d_out;
    float* fc2 = out + (long long)B_ * NN;
    float* g2  = fc2 + (long long)B_ * NN * NN;

    float* h1   = sym_f(d_h1);
    float* g1   = sym_f(d_g1);
    float* h2   = sym_f(d_h2);
    float* el   = sym_f(d_el);
    float* er   = sym_f(d_er);
    float* stat = sym_f(d_stat);
    float* gv   = sym_f(d_gv);

    const dim3 blk(256);
    const int rowsTot = B_ * NN;           // 32768

    // ===== Layer 1 =====
    // h1 = x @ W1   [32768,512]x[512,256]
    sgemm_k<0, 0><<<dim3(H1_ / 128, rowsTot / 128, 1), blk>>>(
        x, W1, h1, H1_, FIN, 0, 0, 0, nullptr, nullptr, nullptr, nullptr);
    rowdot<<<rowsTot / 8, 256>>>(h1, a1, el, er, H1_);
    minmax_stats<<<B_, 256>>>(el, er, stat);
    // g1 = elu(att1 @ h1); att1 computed on the fly from (el, er, stat)
    sgemm_k<1, 1><<<dim3(H1_ / 128, NN / 128, B_), blk>>>(
        nullptr, h1, g1, H1_, NN,
        0, (long long)NN * H1_, (long long)NN * H1_, el, er, stat, nullptr);

    // ===== Layer 2 =====
    // h2 = g1 @ W2   [32768,256]x[256,128]
    sgemm_k<0, 0><<<dim3(H2_ / 128, rowsTot / 128, 1), blk>>>(
        g1, W2, h2, H2_, H1_, 0, 0, 0, nullptr, nullptr, nullptr, nullptr);
    rowdot<<<rowsTot / 8, 256>>>(h2, a2, el, er, H2_);
    minmax_stats<<<B_, 256>>>(el, er, stat);
    // g2 = fc2 @ h2; fc2 computed on the fly AND written out (gridDim.x == 1)
    sgemm_k<2, 0><<<dim3(H2_ / 128, NN / 128, B_), blk>>>(
        nullptr, h2, g2, H2_, NN,
        0, (long long)NN * H2_, (long long)NN * H2_, el, er, stat, fc2);

    // ===== Head: out = leaky(fc2 @ (g2 @ Wg) + bg) =====
    gv_kernel<<<rowsTot / 8, 256>>>(g2, Wg, gv);
    z_kernel<<<rowsTot / 8, 256>>>(fc2, gv, bg, out);
}